// round 2
// baseline (speedup 1.0000x reference)
#include <cuda_runtime.h>
#include <math.h>

#define T_SEQ   8192
#define NBATCH  2
#define NROWS   (NBATCH * T_SEQ)   // 16384
#define WIN     512                // gamma^512 ~ 8.7e-8: truncation safe at 1e-3
#define L2G     (-0.0458037f)      // log2(0.96875)

#define LDQ  132   // padded stride for 128-wide transposed tiles (mult of 4)
#define LDKV 68    // padded stride for 64-wide tiles (mult of 4)

// Scratch (device globals: no allocation allowed in kernel_launch)
__device__ float g_Q[NROWS * 64];
__device__ float g_K[NROWS * 64];
__device__ float g_V[NROWS * 64];
__device__ float g_O[NROWS * 64];

// ---------------------------------------------------------------------------
// Kernel 1: fused QKV projection.  X:[16384,64] @ {W_Q,W_K,W_V}:[64,64]
// Block: 256 threads handles 128 rows. tr=tid&31 -> 4 rows, tc=tid>>5 -> 8 cols.
// ---------------------------------------------------------------------------
__global__ __launch_bounds__(256) void proj_kernel(
    const float* __restrict__ X,
    const float* __restrict__ WQ,
    const float* __restrict__ WK,
    const float* __restrict__ WV)
{
    extern __shared__ float sm[];
    float* XsT = sm;              // [64][LDQ]  (k-major, transposed)
    float* Ws  = sm + 64 * LDQ;   // [3][64][LDKV]

    const int tid = threadIdx.x;
    const int r0  = blockIdx.x * 128;

    for (int idx = tid; idx < 128 * 64; idx += 256) {
        int r = idx >> 6, k = idx & 63;
        XsT[k * LDQ + r] = X[(r0 + r) * 64 + k];
    }
    for (int idx = tid; idx < 64 * 64; idx += 256) {
        int k = idx >> 6, c = idx & 63;
        Ws[0 * 64 * LDKV + k * LDKV + c] = WQ[idx];
        Ws[1 * 64 * LDKV + k * LDKV + c] = WK[idx];
        Ws[2 * 64 * LDKV + k * LDKV + c] = WV[idx];
    }
    __syncthreads();

    const int tr = tid & 31;   // rows 4*tr..4*tr+3
    const int tc = tid >> 5;   // cols 8*tc..8*tc+7

    float* outp[3] = {g_Q, g_K, g_V};

    for (int m = 0; m < 3; m++) {
        float acc[4][8];
        #pragma unroll
        for (int r = 0; r < 4; r++)
            #pragma unroll
            for (int c = 0; c < 8; c++) acc[r][c] = 0.f;

        const float* Wm = Ws + m * 64 * LDKV;
        #pragma unroll 4
        for (int k = 0; k < 64; k++) {
            float4 xv = *(const float4*)&XsT[k * LDQ + 4 * tr];
            float4 w0 = *(const float4*)&Wm[k * LDKV + 8 * tc];
            float4 w1 = *(const float4*)&Wm[k * LDKV + 8 * tc + 4];
            float xr[4] = {xv.x, xv.y, xv.z, xv.w};
            float wc[8] = {w0.x, w0.y, w0.z, w0.w, w1.x, w1.y, w1.z, w1.w};
            #pragma unroll
            for (int r = 0; r < 4; r++)
                #pragma unroll
                for (int c = 0; c < 8; c++)
                    acc[r][c] = fmaf(xr[r], wc[c], acc[r][c]);
        }
        float* op = outp[m];
        #pragma unroll
        for (int r = 0; r < 4; r++) {
            float4 o0 = make_float4(acc[r][0], acc[r][1], acc[r][2], acc[r][3]);
            float4 o1 = make_float4(acc[r][4], acc[r][5], acc[r][6], acc[r][7]);
            float* dst = &op[(r0 + 4 * tr + r) * 64 + 8 * tc];
            *(float4*)dst       = o0;
            *(float4*)(dst + 4) = o1;
        }
    }
}

// ---------------------------------------------------------------------------
// Kernel 2: windowed retention attention.
// CTA = 128 query rows (one batch), loops key tiles of 64 over [t0-WIN, t0+128).
// Score phase: S = (Q K^T) * decay, AV phase: out += S V.
// All inner-loop smem reads are conflict-free LDS.128 or warp-broadcast.
// ---------------------------------------------------------------------------
__global__ __launch_bounds__(256) void attn_kernel()
{
    extern __shared__ float sm[];
    float* QsT   = sm;                      // [64][LDQ]   k-major Q
    float* SsT   = QsT + 64 * LDQ;          // [64][LDQ]   key-major scores
    float* KsT   = SsT + 64 * LDQ;          // [64][LDKV]  k-major K tile
    float* Vs    = KsT + 64 * LDKV;         // [64][LDKV]  key-major V tile
    float* abase = Vs  + 64 * LDKV;         // [128] gamma^i
    float* binv  = abase + 128;             // [64]  gamma^-j

    const int tid = threadIdx.x;
    const int r0  = blockIdx.x * 128;
    const int b   = r0 >> 13;           // / T_SEQ
    const int t0  = r0 & (T_SEQ - 1);

    for (int idx = tid; idx < 128 * 64; idx += 256) {
        int r = idx >> 6, k = idx & 63;
        QsT[k * LDQ + r] = g_Q[(r0 + r) * 64 + k];
    }
    if (tid < 128)       abase[tid] = exp2f((float)tid * L2G);
    else if (tid < 192)  binv[tid - 128] = exp2f(-(float)(tid - 128) * L2G);
    __syncthreads();

    const int tr = tid & 31;   // query rows 4*tr..+3
    const int tc = tid >> 5;   // cols 8*tc..+7 (keys in score, channels in AV)

    float out[4][8];
    #pragma unroll
    for (int r = 0; r < 4; r++)
        #pragma unroll
        for (int c = 0; c < 8; c++) out[r][c] = 0.f;

    int ks = t0 - WIN; if (ks < 0) ks = 0;

    for (int s0 = ks; s0 < t0 + 128; s0 += 64) {
        // --- load K (transposed) and V tiles ---
        for (int idx = tid; idx < 64 * 64; idx += 256) {
            int j = idx >> 6, k = idx & 63;
            const int base = (b * T_SEQ + s0 + j) * 64;
            KsT[k * LDKV + j] = g_K[base + k];
            Vs[j * LDKV + k]  = g_V[base + k];
        }
        __syncthreads();

        // --- score: S[i][j] = dot(Q_i, K_j) ---
        float sc[4][8];
        #pragma unroll
        for (int r = 0; r < 4; r++)
            #pragma unroll
            for (int c = 0; c < 8; c++) sc[r][c] = 0.f;

        #pragma unroll 4
        for (int k = 0; k < 64; k++) {
            float4 qv = *(const float4*)&QsT[k * LDQ + 4 * tr];
            float4 k0 = *(const float4*)&KsT[k * LDKV + 8 * tc];
            float4 k1 = *(const float4*)&KsT[k * LDKV + 8 * tc + 4];
            float qr[4] = {qv.x, qv.y, qv.z, qv.w};
            float kc[8] = {k0.x, k0.y, k0.z, k0.w, k1.x, k1.y, k1.z, k1.w};
            #pragma unroll
            for (int r = 0; r < 4; r++)
                #pragma unroll
                for (int c = 0; c < 8; c++)
                    sc[r][c] = fmaf(qr[r], kc[c], sc[r][c]);
        }

        // --- scale by decay, apply causal mask, store key-major ---
        const float tilefac = exp2f((float)(t0 - s0) * L2G);
        const int   drel    = s0 - t0;   // causal: i >= drel + j
        float ar[4];
        #pragma unroll
        for (int r = 0; r < 4; r++) ar[r] = abase[4 * tr + r];

        #pragma unroll
        for (int jj = 0; jj < 8; jj++) {
            int j = 8 * tc + jj;
            float bj = binv[j] * tilefac;
            int lim = drel + j;
            float4 v;
            v.x = (4 * tr + 0 >= lim) ? sc[0][jj] * ar[0] * bj : 0.f;
            v.y = (4 * tr + 1 >= lim) ? sc[1][jj] * ar[1] * bj : 0.f;
            v.z = (4 * tr + 2 >= lim) ? sc[2][jj] * ar[2] * bj : 0.f;
            v.w = (4 * tr + 3 >= lim) ? sc[3][jj] * ar[3] * bj : 0.f;
            *(float4*)&SsT[j * LDQ + 4 * tr] = v;
        }
        __syncthreads();

        // --- AV: out[i][c] += sum_j S[i][j] * V[j][c] ---
        #pragma unroll 4
        for (int k = 0; k < 64; k++) {
            float4 sv = *(const float4*)&SsT[k * LDQ + 4 * tr];
            float4 v0 = *(const float4*)&Vs[k * LDKV + 8 * tc];
            float4 v1 = *(const float4*)&Vs[k * LDKV + 8 * tc + 4];
            float sr[4] = {sv.x, sv.y, sv.z, sv.w};
            float vc[8] = {v0.x, v0.y, v0.z, v0.w, v1.x, v1.y, v1.z, v1.w};
            #pragma unroll
            for (int r = 0; r < 4; r++)
                #pragma unroll
                for (int c = 0; c < 8; c++)
                    out[r][c] = fmaf(sr[r], vc[c], out[r][c]);
        }
        __syncthreads();
    }

    #pragma unroll
    for (int r = 0; r < 4; r++) {
        float4 o0 = make_float4(out[r][0], out[r][1], out[r][2], out[r][3]);
        float4 o1 = make_float4(out[r][4], out[r][5], out[r][6], out[r][7]);
        float* dst = &g_O[(r0 + 4 * tr + r) * 64 + 8 * tc];
        *(float4*)dst       = o0;
        *(float4*)(dst + 4) = o1;
    }
}

// ---------------------------------------------------------------------------
// Kernel 3: GroupNorm (8 groups x 8 ch, biased var) + transpose-scatter store.
// Reference: gn(out).swapaxes(-2,-1).reshape => write gn[b,t,c] to b*T*C + c*T + t.
// Thread = (group g, t-lane tt); writes coalesced over t.
// ---------------------------------------------------------------------------
__global__ __launch_bounds__(256) void gn_kernel(
    const float* __restrict__ gw, const float* __restrict__ gb,
    float* __restrict__ out)
{
    const int tid = threadIdx.x;
    const int tt  = tid & 31;
    const int g   = tid >> 5;            // 0..7
    const int row = blockIdx.x * 32 + tt;
    const int b   = row >> 13;
    const int t   = row & (T_SEQ - 1);

    const float* x = &g_O[row * 64 + g * 8];
    float v[8];
    float s = 0.f;
    #pragma unroll
    for (int u = 0; u < 8; u++) { v[u] = x[u]; s += v[u]; }
    float mu = s * 0.125f;
    float var = 0.f;
    #pragma unroll
    for (int u = 0; u < 8; u++) { float d = v[u] - mu; var = fmaf(d, d, var); }
    var *= 0.125f;
    float rs = rsqrtf(var + 1e-6f);

    #pragma unroll
    for (int u = 0; u < 8; u++) {
        int c = g * 8 + u;
        out[(size_t)b * T_SEQ * 64 + (size_t)c * T_SEQ + t] =
            (v[u] - mu) * rs * gw[c] + gb[c];
    }
}

// ---------------------------------------------------------------------------
extern "C" void kernel_launch(void* const* d_in, const int* in_sizes, int n_in,
                              void* d_out, int out_size)
{
    (void)in_sizes; (void)n_in; (void)out_size;
    const float* X  = (const float*)d_in[0];
    const float* WQ = (const float*)d_in[1];
    const float* WK = (const float*)d_in[2];
    const float* WV = (const float*)d_in[3];
    const float* gw = (const float*)d_in[4];
    const float* gb = (const float*)d_in[5];
    float* out = (float*)d_out;

    const int PROJ_SMEM = (64 * LDQ + 3 * 64 * LDKV) * 4;             // 86016 B
    const int ATTN_SMEM = (2 * 64 * LDQ + 2 * 64 * LDKV + 192) * 4;   // 103168 B

    cudaFuncSetAttribute(proj_kernel, cudaFuncAttributeMaxDynamicSharedMemorySize, PROJ_SMEM);
    cudaFuncSetAttribute(attn_kernel, cudaFuncAttributeMaxDynamicSharedMemorySize, ATTN_SMEM);

    proj_kernel<<<NROWS / 128, 256, PROJ_SMEM>>>(X, WQ, WK, WV);
    attn_kernel<<<NROWS / 128, 256, ATTN_SMEM>>>();
    gn_kernel<<<NROWS / 32, 256>>>(gw, gb, out);
}

// round 8
// speedup vs baseline: 2.3618x; 2.3618x over previous
#include <cuda_runtime.h>
#include <math.h>

#define T_SEQ   8192
#define NBATCH  2
#define NROWS   (NBATCH * T_SEQ)   // 16384
#define WIN     512                // gamma^512 ~ 8.7e-8: truncation safe at 1e-3
#define L2G     (-0.04580369f)     // log2(0.96875)

// ---------------- scratch (device globals; no allocs allowed) ----------------
__device__ float g_Q[NROWS * 64];
__device__ float g_K[NROWS * 64];
__device__ float g_V[NROWS * 64];
__device__ float g_O[NROWS * 64];

__device__ __forceinline__ float to_tf32(float x) {
    unsigned u; asm("cvt.rna.tf32.f32 %0, %1;" : "=r"(u) : "f"(x));
    return __uint_as_float(u);
}

// m16n8k8 tf32 warp MMA (family-agnostic PTX, compiles for compute_103)
__device__ __forceinline__ void mma_tf32(float& d0, float& d1, float& d2, float& d3,
                                         unsigned a0, unsigned a1, unsigned a2, unsigned a3,
                                         unsigned b0, unsigned b1) {
    asm volatile("mma.sync.aligned.m16n8k8.row.col.f32.tf32.tf32.f32 "
                 "{%0,%1,%2,%3}, {%4,%5,%6,%7}, {%8,%9}, {%0,%1,%2,%3};"
                 : "+f"(d0), "+f"(d1), "+f"(d2), "+f"(d3)
                 : "r"(a0), "r"(a1), "r"(a2), "r"(a3), "r"(b0), "r"(b1));
}

// ============================ Kernel 1: QKV proj =============================
#define LDX 68
__global__ __launch_bounds__(256) void proj_kernel(
    const float* __restrict__ X,
    const float* __restrict__ WQ,
    const float* __restrict__ WK,
    const float* __restrict__ WV)
{
    extern __shared__ float sm[];
    float* XsT = sm;               // [64 k][LDX] rows 0..63
    float* Ws  = sm + 64 * LDX;    // [3][64 k][LDX]

    const int tid = threadIdx.x;
    const int r0  = blockIdx.x * 64;

    for (int idx = tid; idx < 64 * 16; idx += 256) {
        int row = idx >> 4, c4 = (idx & 15) << 2;
        float4 v = *(const float4*)&X[(r0 + row) * 64 + c4];
        XsT[(c4 + 0) * LDX + row] = v.x;
        XsT[(c4 + 1) * LDX + row] = v.y;
        XsT[(c4 + 2) * LDX + row] = v.z;
        XsT[(c4 + 3) * LDX + row] = v.w;
    }
    for (int idx = tid; idx < 64 * 64; idx += 256) {
        int k = idx >> 6, c = idx & 63;
        Ws[(0 * 64 + k) * LDX + c] = WQ[idx];
        Ws[(1 * 64 + k) * LDX + c] = WK[idx];
        Ws[(2 * 64 + k) * LDX + c] = WV[idx];
    }
    __syncthreads();

    const int tr = tid & 15;   // rows 4tr..+3
    const int tc = tid >> 4;   // cols 4tc..+3
    float* outp[3] = {g_Q, g_K, g_V};

    for (int m = 0; m < 3; m++) {
        float acc[4][4];
        #pragma unroll
        for (int r = 0; r < 4; r++)
            #pragma unroll
            for (int c = 0; c < 4; c++) acc[r][c] = 0.f;

        const float* Wm = Ws + m * 64 * LDX;
        #pragma unroll 8
        for (int k = 0; k < 64; k++) {
            float4 xv = *(const float4*)&XsT[k * LDX + 4 * tr];
            float4 wv = *(const float4*)&Wm[k * LDX + 4 * tc];
            float xr[4] = {xv.x, xv.y, xv.z, xv.w};
            float wc[4] = {wv.x, wv.y, wv.z, wv.w};
            #pragma unroll
            for (int r = 0; r < 4; r++)
                #pragma unroll
                for (int c = 0; c < 4; c++)
                    acc[r][c] = fmaf(xr[r], wc[c], acc[r][c]);
        }
        float* op = outp[m];
        #pragma unroll
        for (int r = 0; r < 4; r++)
            *(float4*)&op[(r0 + 4 * tr + r) * 64 + 4 * tc] =
                make_float4(acc[r][0], acc[r][1], acc[r][2], acc[r][3]);
    }
}

// ====================== Kernel 2: warp-MMA tf32 attention ====================
// CTA = 128 query rows, 8 warps x 16 rows. Key tiles of 64.
// Stage1: S = Q K^T (m16n8k8 tf32), epilogue decay+mask in C-frags,
// S -> warp-private smem (tf32), Stage2: O += S V.
#define LDP 68   // pad for Q/K/S  (bank = lane + const for all frag loads)
#define LDV 72   // pad for V      (bank = 8*(lane%4)+lane/4 + const)

// smem floats: binv[64] | Qs[128*LDP] | Ks[64*LDP] | Vs[64*LDV] | Ss[8*16*LDP]
#define SM_BINV 0
#define SM_QS   64
#define SM_KS   (SM_QS + 128 * LDP)
#define SM_VS   (SM_KS + 64 * LDP)
#define SM_SS   (SM_VS + 64 * LDV)
#define ATTN_SMEM_FLOATS (SM_SS + 8 * 16 * LDP)
#define ATTN_SMEM (ATTN_SMEM_FLOATS * 4)   // 105728 B

__global__ __launch_bounds__(256) void attn_kernel()
{
    extern __shared__ float sm[];
    float* binv = sm + SM_BINV;
    float* Qs   = sm + SM_QS;
    float* Ks   = sm + SM_KS;
    float* Vs   = sm + SM_VS;

    const int tid  = threadIdx.x;
    const int lane = tid & 31;
    const int w    = tid >> 5;
    const int gi   = lane >> 2;   // 0..7  (fragment row group)
    const int ti4  = lane & 3;    // 0..3  (fragment col group)

    const int r0 = blockIdx.x * 128;
    const int b  = r0 >> 13;
    const int t0 = r0 & (T_SEQ - 1);
    const int bT = b << 13;

    if (tid < 64) binv[tid] = exp2f(-(float)tid * L2G);   // gamma^-j

    // ---- stage Q (tf32) ----
    for (int idx = tid; idx < 128 * 16; idx += 256) {
        int row = idx >> 4, c4 = (idx & 15) << 2;
        float4 v = *(const float4*)&g_Q[(r0 + row) * 64 + c4];
        v.x = to_tf32(v.x); v.y = to_tf32(v.y); v.z = to_tf32(v.z); v.w = to_tf32(v.w);
        *(float4*)&Qs[row * LDP + c4] = v;
    }
    __syncthreads();

    // ---- Q fragments, register-resident for all tiles ----
    const int qr = w * 16;
    unsigned qa[8][4];
    #pragma unroll
    for (int k0 = 0; k0 < 8; k0++) {
        int base = (qr + gi) * LDP + k0 * 8 + ti4;
        qa[k0][0] = __float_as_uint(Qs[base]);
        qa[k0][1] = __float_as_uint(Qs[base + 8 * LDP]);
        qa[k0][2] = __float_as_uint(Qs[base + 4]);
        qa[k0][3] = __float_as_uint(Qs[base + 8 * LDP + 4]);
    }

    float o[8][4];
    #pragma unroll
    for (int nt = 0; nt < 8; nt++)
        #pragma unroll
        for (int u = 0; u < 4; u++) o[nt][u] = 0.f;

    float* sw = sm + SM_SS + w * 16 * LDP;   // warp-private S buffer
    int ks = t0 - WIN; if (ks < 0) ks = 0;

    for (int s0 = ks; s0 < t0 + 128; s0 += 64) {
        // ---- stage K, V tiles (tf32) ----
        for (int idx = tid; idx < 64 * 16; idx += 256) {
            int key = idx >> 4, c4 = (idx & 15) << 2;
            float4 kv = *(const float4*)&g_K[(bT + s0 + key) * 64 + c4];
            kv.x = to_tf32(kv.x); kv.y = to_tf32(kv.y);
            kv.z = to_tf32(kv.z); kv.w = to_tf32(kv.w);
            *(float4*)&Ks[key * LDP + c4] = kv;
            float4 vv = *(const float4*)&g_V[(bT + s0 + key) * 64 + c4];
            vv.x = to_tf32(vv.x); vv.y = to_tf32(vv.y);
            vv.z = to_tf32(vv.z); vv.w = to_tf32(vv.w);
            *(float4*)&Vs[key * LDV + c4] = vv;
        }
        __syncthreads();

        const int   dr0 = t0 + qr + gi - s0;          // iglob - s0, row a
        const float ai0 = exp2f((float)dr0 * L2G);
        const float ai1 = exp2f((float)(dr0 + 8) * L2G);

        // ---- stage 1: S = Q K^T, decay+mask epilogue, store tf32 to Ss ----
        #pragma unroll
        for (int nt = 0; nt < 8; nt++) {
            float c0 = 0.f, c1 = 0.f, c2 = 0.f, c3 = 0.f;
            #pragma unroll
            for (int k0 = 0; k0 < 8; k0++) {
                int ba = (nt * 8 + gi) * LDP + k0 * 8 + ti4;
                unsigned b0 = __float_as_uint(Ks[ba]);
                unsigned b1 = __float_as_uint(Ks[ba + 4]);
                mma_tf32(c0, c1, c2, c3,
                         qa[k0][0], qa[k0][1], qa[k0][2], qa[k0][3], b0, b1);
            }
            const int je = nt * 8 + 2 * ti4, jo = je + 1;
            const float be = binv[je], bo = binv[jo];
            c0 = (dr0     >= je) ? c0 * ai0 * be : 0.f;
            c1 = (dr0     >= jo) ? c1 * ai0 * bo : 0.f;
            c2 = (dr0 + 8 >= je) ? c2 * ai1 * be : 0.f;
            c3 = (dr0 + 8 >= jo) ? c3 * ai1 * bo : 0.f;
            *(float2*)&sw[gi * LDP + je] = make_float2(to_tf32(c0), to_tf32(c1));
            *(float2*)&sw[(gi + 8) * LDP + je] = make_float2(to_tf32(c2), to_tf32(c3));
        }
        __syncwarp();

        // ---- A fragments of S ----
        unsigned sa[8][4];
        #pragma unroll
        for (int k0 = 0; k0 < 8; k0++) {
            int base = gi * LDP + k0 * 8 + ti4;
            sa[k0][0] = __float_as_uint(sw[base]);
            sa[k0][1] = __float_as_uint(sw[base + 8 * LDP]);
            sa[k0][2] = __float_as_uint(sw[base + 4]);
            sa[k0][3] = __float_as_uint(sw[base + 8 * LDP + 4]);
        }

        // ---- stage 2: O += S V ----
        #pragma unroll
        for (int nt = 0; nt < 8; nt++) {
            #pragma unroll
            for (int k0 = 0; k0 < 8; k0++) {
                int va = (k0 * 8 + ti4) * LDV + nt * 8 + gi;
                unsigned b0 = __float_as_uint(Vs[va]);
                unsigned b1 = __float_as_uint(Vs[va + 4 * LDV]);
                mma_tf32(o[nt][0], o[nt][1], o[nt][2], o[nt][3],
                         sa[k0][0], sa[k0][1], sa[k0][2], sa[k0][3], b0, b1);
            }
        }
        __syncthreads();
    }

    // ---- write O ----
    const int row0 = r0 + qr + gi;
    #pragma unroll
    for (int nt = 0; nt < 8; nt++) {
        int col = nt * 8 + 2 * ti4;
        *(float2*)&g_O[row0 * 64 + col]       = make_float2(o[nt][0], o[nt][1]);
        *(float2*)&g_O[(row0 + 8) * 64 + col] = make_float2(o[nt][2], o[nt][3]);
    }
}

// ========================= Kernel 3: GroupNorm ===============================
__global__ __launch_bounds__(256) void gn_kernel(
    const float* __restrict__ gw, const float* __restrict__ gb,
    float* __restrict__ out)
{
    const int tid = threadIdx.x;
    const int tt  = tid & 31;
    const int g   = tid >> 5;            // 0..7
    const int row = blockIdx.x * 32 + tt;
    const int b   = row >> 13;
    const int t   = row & (T_SEQ - 1);

    const float* x = &g_O[row * 64 + g * 8];
    float v[8];
    float s = 0.f;
    #pragma unroll
    for (int u = 0; u < 8; u++) { v[u] = x[u]; s += v[u]; }
    float mu = s * 0.125f;
    float var = 0.f;
    #pragma unroll
    for (int u = 0; u < 8; u++) { float d = v[u] - mu; var = fmaf(d, d, var); }
    var *= 0.125f;
    float rs = rsqrtf(var + 1e-6f);

    #pragma unroll
    for (int u = 0; u < 8; u++) {
        int c = g * 8 + u;
        out[(size_t)b * T_SEQ * 64 + (size_t)c * T_SEQ + t] =
            (v[u] - mu) * rs * gw[c] + gb[c];
    }
}

// =============================================================================
extern "C" void kernel_launch(void* const* d_in, const int* in_sizes, int n_in,
                              void* d_out, int out_size)
{
    (void)in_sizes; (void)n_in; (void)out_size;
    const float* X  = (const float*)d_in[0];
    const float* WQ = (const float*)d_in[1];
    const float* WK = (const float*)d_in[2];
    const float* WV = (const float*)d_in[3];
    const float* gw = (const float*)d_in[4];
    const float* gb = (const float*)d_in[5];
    float* out = (float*)d_out;

    const int PROJ_SMEM = 4 * 64 * LDX * 4;   // 69632 B

    cudaFuncSetAttribute(proj_kernel, cudaFuncAttributeMaxDynamicSharedMemorySize, PROJ_SMEM);
    cudaFuncSetAttribute(attn_kernel, cudaFuncAttributeMaxDynamicSharedMemorySize, ATTN_SMEM);

    proj_kernel<<<NROWS / 64, 256, PROJ_SMEM>>>(X, WQ, WK, WV);
    attn_kernel<<<NROWS / 128, 256, ATTN_SMEM>>>();
    gn_kernel<<<NROWS / 32, 256>>>(gw, gb, out);
}

// round 11
// speedup vs baseline: 3.2583x; 1.3796x over previous
#include <cuda_runtime.h>
#include <math.h>

#define T_SEQ   8192
#define NBATCH  2
#define NROWS   (NBATCH * T_SEQ)   // 16384
#define WIN     512                // gamma^512 ~ 8.7e-8: truncation safe at 1e-3
#define L2G     (-0.04580369f)     // log2(0.96875)

// ---------------- scratch (device globals; no allocs allowed) ----------------
__device__ float g_Q[NROWS * 64];
__device__ float g_K[NROWS * 64];
__device__ float g_V[NROWS * 64];
__device__ float g_O[NROWS * 64];

__device__ __forceinline__ float to_tf32(float x) {
    unsigned u; asm("cvt.rna.tf32.f32 %0, %1;" : "=r"(u) : "f"(x));
    return __uint_as_float(u);
}

// m16n8k8 tf32 warp MMA (family-agnostic PTX, compiles for compute_103)
__device__ __forceinline__ void mma_tf32(float& d0, float& d1, float& d2, float& d3,
                                         unsigned a0, unsigned a1, unsigned a2, unsigned a3,
                                         unsigned b0, unsigned b1) {
    asm volatile("mma.sync.aligned.m16n8k8.row.col.f32.tf32.tf32.f32 "
                 "{%0,%1,%2,%3}, {%4,%5,%6,%7}, {%8,%9}, {%0,%1,%2,%3};"
                 : "+f"(d0), "+f"(d1), "+f"(d2), "+f"(d3)
                 : "r"(a0), "r"(a1), "r"(a2), "r"(a3), "r"(b0), "r"(b1));
}

// =================== Kernel 1: QKV proj (3xTF32 tensor-core) =================
// Y[16384,192] = X @ [WQ|WK|WV], error-compensated: AhBh + AhBl + AlBh.
// CTA: 128 threads (4 warps x 16 rows = 64 rows), grid 256.
#define LDXP 68    // X smem pad: frag banks gi*4+ti4 -> conflict-free
#define LDW  200   // W smem pad: 200 mod 32 = 8 -> frag banks ti4*8+gi -> CF
#define PROJ_SMEM ((64 * LDXP + 64 * LDW) * 4)   // 68608 B

__global__ __launch_bounds__(128, 3) void proj_kernel(
    const float* __restrict__ X,
    const float* __restrict__ WQ,
    const float* __restrict__ WK,
    const float* __restrict__ WV)
{
    extern __shared__ float sm[];
    float* Xs = sm;                // [64][LDXP]
    float* Ws = sm + 64 * LDXP;    // [64 k][LDW], cols 0..191 = WQ|WK|WV

    const int tid  = threadIdx.x;
    const int lane = tid & 31;
    const int w    = tid >> 5;
    const int gi   = lane >> 2;
    const int ti4  = lane & 3;
    const int r0   = blockIdx.x * 64;

    for (int idx = tid; idx < 64 * 16; idx += 128) {
        int row = idx >> 4, c4 = (idx & 15) << 2;
        *(float4*)&Xs[row * LDXP + c4] = *(const float4*)&X[(r0 + row) * 64 + c4];
    }
    {
        const float* Wsrc[3] = {WQ, WK, WV};
        #pragma unroll
        for (int m = 0; m < 3; m++)
            for (int idx = tid; idx < 64 * 16; idx += 128) {
                int row = idx >> 4, c4 = (idx & 15) << 2;
                *(float4*)&Ws[row * LDW + m * 64 + c4] =
                    *(const float4*)&Wsrc[m][row * 64 + c4];
            }
    }
    __syncthreads();

    // A fragments: hi/lo split of X rows (qrow, qrow+8)
    const int qrow = w * 16 + gi;
    unsigned ahi[8][4], alo[8][4];
    #pragma unroll
    for (int k0 = 0; k0 < 8; k0++) {
        float xv[4];
        xv[0] = Xs[qrow * LDXP + k0 * 8 + ti4];
        xv[1] = Xs[(qrow + 8) * LDXP + k0 * 8 + ti4];
        xv[2] = Xs[qrow * LDXP + k0 * 8 + ti4 + 4];
        xv[3] = Xs[(qrow + 8) * LDXP + k0 * 8 + ti4 + 4];
        #pragma unroll
        for (int u = 0; u < 4; u++) {
            float hi = to_tf32(xv[u]);
            ahi[k0][u] = __float_as_uint(hi);
            alo[k0][u] = __float_as_uint(to_tf32(xv[u] - hi));
        }
    }

    float* outp[3] = {g_Q, g_K, g_V};
    for (int m = 0; m < 3; m++) {
        float acc[8][4];
        #pragma unroll
        for (int nt = 0; nt < 8; nt++)
            #pragma unroll
            for (int u = 0; u < 4; u++) acc[nt][u] = 0.f;

        #pragma unroll
        for (int nt = 0; nt < 8; nt++) {
            const int ncol = m * 64 + nt * 8 + gi;
            #pragma unroll
            for (int k0 = 0; k0 < 8; k0++) {
                float b0f = Ws[(k0 * 8 + ti4) * LDW + ncol];
                float b1f = Ws[(k0 * 8 + ti4 + 4) * LDW + ncol];
                float b0h = to_tf32(b0f), b1h = to_tf32(b1f);
                unsigned ub0h = __float_as_uint(b0h);
                unsigned ub1h = __float_as_uint(b1h);
                unsigned ub0l = __float_as_uint(to_tf32(b0f - b0h));
                unsigned ub1l = __float_as_uint(to_tf32(b1f - b1h));
                mma_tf32(acc[nt][0], acc[nt][1], acc[nt][2], acc[nt][3],
                         ahi[k0][0], ahi[k0][1], ahi[k0][2], ahi[k0][3], ub0h, ub1h);
                mma_tf32(acc[nt][0], acc[nt][1], acc[nt][2], acc[nt][3],
                         ahi[k0][0], ahi[k0][1], ahi[k0][2], ahi[k0][3], ub0l, ub1l);
                mma_tf32(acc[nt][0], acc[nt][1], acc[nt][2], acc[nt][3],
                         alo[k0][0], alo[k0][1], alo[k0][2], alo[k0][3], ub0h, ub1h);
            }
        }
        float* op = outp[m];
        #pragma unroll
        for (int nt = 0; nt < 8; nt++) {
            int col = nt * 8 + 2 * ti4;
            *(float2*)&op[(r0 + qrow) * 64 + col]     = make_float2(acc[nt][0], acc[nt][1]);
            *(float2*)&op[(r0 + qrow + 8) * 64 + col] = make_float2(acc[nt][2], acc[nt][3]);
        }
    }
}

// ====================== Kernel 2: warp-MMA tf32 attention ====================
// CTA = 64 query rows, 4 warps x 16 rows, 128 threads, grid 256. Key tiles 64.
// S-buffer aliases Qs (Q is register-resident after frag load) -> 53.5KB smem,
// 3 CTAs/SM.
#define LDP 68   // pad for Q/K/S
#define LDV 72   // pad for V

#define SM_BINV 0
#define SM_QS   64                      // [64][LDP]; reused as S buffer
#define SM_KS   (SM_QS + 64 * LDP)      // [64][LDP]
#define SM_VS   (SM_KS + 64 * LDP)      // [64][LDV]
#define ATTN_SMEM ((SM_VS + 64 * LDV) * 4)   // 53504 B

__global__ __launch_bounds__(128, 3) void attn_kernel()
{
    extern __shared__ float sm[];
    float* binv = sm + SM_BINV;
    float* Qs   = sm + SM_QS;
    float* Ks   = sm + SM_KS;
    float* Vs   = sm + SM_VS;

    const int tid  = threadIdx.x;
    const int lane = tid & 31;
    const int w    = tid >> 5;
    const int gi   = lane >> 2;   // 0..7
    const int ti4  = lane & 3;    // 0..3

    const int r0 = blockIdx.x * 64;
    const int b  = r0 >> 13;
    const int t0 = r0 & (T_SEQ - 1);
    const int bT = b << 13;

    if (tid < 64) binv[tid] = exp2f(-(float)tid * L2G);   // gamma^-j

    // ---- stage Q (tf32) ----
    for (int idx = tid; idx < 64 * 16; idx += 128) {
        int row = idx >> 4, c4 = (idx & 15) << 2;
        float4 v = *(const float4*)&g_Q[(r0 + row) * 64 + c4];
        v.x = to_tf32(v.x); v.y = to_tf32(v.y); v.z = to_tf32(v.z); v.w = to_tf32(v.w);
        *(float4*)&Qs[row * LDP + c4] = v;
    }
    __syncthreads();

    // ---- Q fragments, register-resident for all tiles ----
    const int qr = w * 16;
    unsigned qa[8][4];
    #pragma unroll
    for (int k0 = 0; k0 < 8; k0++) {
        int base = (qr + gi) * LDP + k0 * 8 + ti4;
        qa[k0][0] = __float_as_uint(Qs[base]);
        qa[k0][1] = __float_as_uint(Qs[base + 8 * LDP]);
        qa[k0][2] = __float_as_uint(Qs[base + 4]);
        qa[k0][3] = __float_as_uint(Qs[base + 8 * LDP + 4]);
    }

    float o[8][4];
    #pragma unroll
    for (int nt = 0; nt < 8; nt++)
        #pragma unroll
        for (int u = 0; u < 4; u++) o[nt][u] = 0.f;

    float* sw = Qs + qr * LDP;      // warp-private S buffer (aliases this warp's Q rows)
    int ks = t0 - WIN; if (ks < 0) ks = 0;

    for (int s0 = ks; s0 < t0 + 64; s0 += 64) {
        // ---- stage K, V tiles (tf32) ----
        for (int idx = tid; idx < 64 * 16; idx += 128) {
            int key = idx >> 4, c4 = (idx & 15) << 2;
            float4 kv = *(const float4*)&g_K[(bT + s0 + key) * 64 + c4];
            kv.x = to_tf32(kv.x); kv.y = to_tf32(kv.y);
            kv.z = to_tf32(kv.z); kv.w = to_tf32(kv.w);
            *(float4*)&Ks[key * LDP + c4] = kv;
            float4 vv = *(const float4*)&g_V[(bT + s0 + key) * 64 + c4];
            vv.x = to_tf32(vv.x); vv.y = to_tf32(vv.y);
            vv.z = to_tf32(vv.z); vv.w = to_tf32(vv.w);
            *(float4*)&Vs[key * LDV + c4] = vv;
        }
        __syncthreads();

        const int   dr0 = t0 + qr + gi - s0;          // iglob - s0, row a
        const float ai0 = exp2f((float)dr0 * L2G);
        const float ai1 = exp2f((float)(dr0 + 8) * L2G);

        // ---- stage 1: S = Q K^T, decay+mask epilogue, store tf32 to S ----
        #pragma unroll
        for (int nt = 0; nt < 8; nt++) {
            float c0 = 0.f, c1 = 0.f, c2 = 0.f, c3 = 0.f;
            #pragma unroll
            for (int k0 = 0; k0 < 8; k0++) {
                int ba = (nt * 8 + gi) * LDP + k0 * 8 + ti4;
                unsigned b0 = __float_as_uint(Ks[ba]);
                unsigned b1 = __float_as_uint(Ks[ba + 4]);
                mma_tf32(c0, c1, c2, c3,
                         qa[k0][0], qa[k0][1], qa[k0][2], qa[k0][3], b0, b1);
            }
            const int je = nt * 8 + 2 * ti4, jo = je + 1;
            const float be = binv[je], bo = binv[jo];
            c0 = (dr0     >= je) ? c0 * ai0 * be : 0.f;
            c1 = (dr0     >= jo) ? c1 * ai0 * bo : 0.f;
            c2 = (dr0 + 8 >= je) ? c2 * ai1 * be : 0.f;
            c3 = (dr0 + 8 >= jo) ? c3 * ai1 * bo : 0.f;
            *(float2*)&sw[gi * LDP + je] = make_float2(to_tf32(c0), to_tf32(c1));
            *(float2*)&sw[(gi + 8) * LDP + je] = make_float2(to_tf32(c2), to_tf32(c3));
        }
        __syncwarp();

        // ---- A fragments of S ----
        unsigned sa[8][4];
        #pragma unroll
        for (int k0 = 0; k0 < 8; k0++) {
            int base = gi * LDP + k0 * 8 + ti4;
            sa[k0][0] = __float_as_uint(sw[base]);
            sa[k0][1] = __float_as_uint(sw[base + 8 * LDP]);
            sa[k0][2] = __float_as_uint(sw[base + 4]);
            sa[k0][3] = __float_as_uint(sw[base + 8 * LDP + 4]);
        }

        // ---- stage 2: O += S V ----
        #pragma unroll
        for (int nt = 0; nt < 8; nt++) {
            #pragma unroll
            for (int k0 = 0; k0 < 8; k0++) {
                int va = (k0 * 8 + ti4) * LDV + nt * 8 + gi;
                unsigned b0 = __float_as_uint(Vs[va]);
                unsigned b1 = __float_as_uint(Vs[va + 4 * LDV]);
                mma_tf32(o[nt][0], o[nt][1], o[nt][2], o[nt][3],
                         sa[k0][0], sa[k0][1], sa[k0][2], sa[k0][3], b0, b1);
            }
        }
        __syncthreads();
    }

    // ---- write O ----
    const int row0 = r0 + qr + gi;
    #pragma unroll
    for (int nt = 0; nt < 8; nt++) {
        int col = nt * 8 + 2 * ti4;
        *(float2*)&g_O[row0 * 64 + col]       = make_float2(o[nt][0], o[nt][1]);
        *(float2*)&g_O[(row0 + 8) * 64 + col] = make_float2(o[nt][2], o[nt][3]);
    }
}

// ========================= Kernel 3: GroupNorm ===============================
__global__ __launch_bounds__(256) void gn_kernel(
    const float* __restrict__ gw, const float* __restrict__ gb,
    float* __restrict__ out)
{
    const int tid = threadIdx.x;
    const int tt  = tid & 31;
    const int g   = tid >> 5;            // 0..7
    const int row = blockIdx.x * 32 + tt;
    const int b   = row >> 13;
    const int t   = row & (T_SEQ - 1);

    const float* x = &g_O[row * 64 + g * 8];
    float v[8];
    float s = 0.f;
    #pragma unroll
    for (int u = 0; u < 8; u++) { v[u] = x[u]; s += v[u]; }
    float mu = s * 0.125f;
    float var = 0.f;
    #pragma unroll
    for (int u = 0; u < 8; u++) { float d = v[u] - mu; var = fmaf(d, d, var); }
    var *= 0.125f;
    float rs = rsqrtf(var + 1e-6f);

    #pragma unroll
    for (int u = 0; u < 8; u++) {
        int c = g * 8 + u;
        out[(size_t)b * T_SEQ * 64 + (size_t)c * T_SEQ + t] =
            (v[u] - mu) * rs * gw[c] + gb[c];
    }
}

// =============================================================================
extern "C" void kernel_launch(void* const* d_in, const int* in_sizes, int n_in,
                              void* d_out, int out_size)
{
    (void)in_sizes; (void)n_in; (void)out_size;
    const float* X  = (const float*)d_in[0];
    const float* WQ = (const float*)d_in[1];
    const float* WK = (const float*)d_in[2];
    const float* WV = (const float*)d_in[3];
    const float* gw = (const float*)d_in[4];
    const float* gb = (const float*)d_in[5];
    float* out = (float*)d_out;

    cudaFuncSetAttribute(proj_kernel, cudaFuncAttributeMaxDynamicSharedMemorySize, PROJ_SMEM);
    cudaFuncSetAttribute(attn_kernel, cudaFuncAttributeMaxDynamicSharedMemorySize, ATTN_SMEM);

    proj_kernel<<<NROWS / 64, 128, PROJ_SMEM>>>(X, WQ, WK, WV);
    attn_kernel<<<NROWS / 64, 128, ATTN_SMEM>>>();
    gn_kernel<<<NROWS / 32, 256>>>(gw, gb, out);
}

// round 12
// speedup vs baseline: 3.9728x; 1.2193x over previous
#include <cuda_runtime.h>
#include <math.h>

#define T_SEQ   8192
#define NBATCH  2
#define NROWS   (NBATCH * T_SEQ)   // 16384
#define WIN     512                // gamma^512 ~ 8.7e-8: truncation safe at 1e-3
#define L2G     (-0.04580369f)     // log2(0.96875)

// ---------------- scratch (device globals; no allocs allowed) ----------------
__device__ float g_Q[NROWS * 64];
__device__ float g_K[NROWS * 64];
__device__ float g_V[NROWS * 64];

__device__ __forceinline__ float to_tf32(float x) {
    unsigned u; asm("cvt.rna.tf32.f32 %0, %1;" : "=r"(u) : "f"(x));
    return __uint_as_float(u);
}

// m16n8k8 tf32 warp MMA (family-agnostic PTX, compiles for compute_103)
__device__ __forceinline__ void mma_tf32(float& d0, float& d1, float& d2, float& d3,
                                         unsigned a0, unsigned a1, unsigned a2, unsigned a3,
                                         unsigned b0, unsigned b1) {
    asm volatile("mma.sync.aligned.m16n8k8.row.col.f32.tf32.tf32.f32 "
                 "{%0,%1,%2,%3}, {%4,%5,%6,%7}, {%8,%9}, {%0,%1,%2,%3};"
                 : "+f"(d0), "+f"(d1), "+f"(d2), "+f"(d3)
                 : "r"(a0), "r"(a1), "r"(a2), "r"(a3), "r"(b0), "r"(b1));
}

// =================== Kernel 1: QKV proj (3xTF32 tensor-core) =================
// Y[16384,192] = X @ [WQ|WK|WV], error-compensated: AhBh + (AhBl + AlBh).
// CTA: 256 threads, 8 warps. Warp = (row group wr=w&3)*16 rows x (col half wh=w>>2).
// Two accumulator banks break the MMA dependency chain.
#define LDXP 68    // X smem pad: frag banks gi*4+ti4 -> conflict-free
#define LDW  200   // W smem pad: 200 mod 32 = 8 -> frag banks ti4*8+gi -> CF
#define PROJ_SMEM ((64 * LDXP + 64 * LDW) * 4)   // 68608 B

__global__ __launch_bounds__(256, 2) void proj_kernel(
    const float* __restrict__ X,
    const float* __restrict__ WQ,
    const float* __restrict__ WK,
    const float* __restrict__ WV)
{
    extern __shared__ float sm[];
    float* Xs = sm;                // [64][LDXP]
    float* Ws = sm + 64 * LDXP;    // [64 k][LDW], cols 0..191 = WQ|WK|WV

    const int tid  = threadIdx.x;
    const int lane = tid & 31;
    const int w    = tid >> 5;
    const int gi   = lane >> 2;
    const int ti4  = lane & 3;
    const int wr   = w & 3;        // row group
    const int wh   = w >> 2;       // column half (0: nt 0-3, 1: nt 4-7)
    const int r0   = blockIdx.x * 64;

    for (int idx = tid; idx < 64 * 16; idx += 256) {
        int row = idx >> 4, c4 = (idx & 15) << 2;
        *(float4*)&Xs[row * LDXP + c4] = *(const float4*)&X[(r0 + row) * 64 + c4];
    }
    {
        const float* Wsrc[3] = {WQ, WK, WV};
        #pragma unroll
        for (int m = 0; m < 3; m++)
            for (int idx = tid; idx < 64 * 16; idx += 256) {
                int row = idx >> 4, c4 = (idx & 15) << 2;
                *(float4*)&Ws[row * LDW + m * 64 + c4] =
                    *(const float4*)&Wsrc[m][row * 64 + c4];
            }
    }
    __syncthreads();

    // A fragments: hi/lo split of X rows (qrow, qrow+8)
    const int qrow = wr * 16 + gi;
    unsigned ahi[8][4], alo[8][4];
    #pragma unroll
    for (int k0 = 0; k0 < 8; k0++) {
        float xv[4];
        xv[0] = Xs[qrow * LDXP + k0 * 8 + ti4];
        xv[1] = Xs[(qrow + 8) * LDXP + k0 * 8 + ti4];
        xv[2] = Xs[qrow * LDXP + k0 * 8 + ti4 + 4];
        xv[3] = Xs[(qrow + 8) * LDXP + k0 * 8 + ti4 + 4];
        #pragma unroll
        for (int u = 0; u < 4; u++) {
            float hi = to_tf32(xv[u]);
            ahi[k0][u] = __float_as_uint(hi);
            alo[k0][u] = __float_as_uint(to_tf32(xv[u] - hi));
        }
    }

    float* outp[3] = {g_Q, g_K, g_V};
    for (int m = 0; m < 3; m++) {
        float accA[4][4], accB[4][4];
        #pragma unroll
        for (int nt = 0; nt < 4; nt++)
            #pragma unroll
            for (int u = 0; u < 4; u++) { accA[nt][u] = 0.f; accB[nt][u] = 0.f; }

        #pragma unroll
        for (int k0 = 0; k0 < 8; k0++) {
            #pragma unroll
            for (int ntl = 0; ntl < 4; ntl++) {
                const int ncol = m * 64 + (wh * 4 + ntl) * 8 + gi;
                float b0f = Ws[(k0 * 8 + ti4) * LDW + ncol];
                float b1f = Ws[(k0 * 8 + ti4 + 4) * LDW + ncol];
                float b0h = to_tf32(b0f), b1h = to_tf32(b1f);
                unsigned ub0h = __float_as_uint(b0h);
                unsigned ub1h = __float_as_uint(b1h);
                unsigned ub0l = __float_as_uint(to_tf32(b0f - b0h));
                unsigned ub1l = __float_as_uint(to_tf32(b1f - b1h));
                mma_tf32(accA[ntl][0], accA[ntl][1], accA[ntl][2], accA[ntl][3],
                         ahi[k0][0], ahi[k0][1], ahi[k0][2], ahi[k0][3], ub0h, ub1h);
                mma_tf32(accB[ntl][0], accB[ntl][1], accB[ntl][2], accB[ntl][3],
                         ahi[k0][0], ahi[k0][1], ahi[k0][2], ahi[k0][3], ub0l, ub1l);
                mma_tf32(accB[ntl][0], accB[ntl][1], accB[ntl][2], accB[ntl][3],
                         alo[k0][0], alo[k0][1], alo[k0][2], alo[k0][3], ub0h, ub1h);
            }
        }
        float* op = outp[m];
        #pragma unroll
        for (int ntl = 0; ntl < 4; ntl++) {
            int col = (wh * 4 + ntl) * 8 + 2 * ti4;
            *(float2*)&op[(r0 + qrow) * 64 + col] =
                make_float2(accA[ntl][0] + accB[ntl][0], accA[ntl][1] + accB[ntl][1]);
            *(float2*)&op[(r0 + qrow + 8) * 64 + col] =
                make_float2(accA[ntl][2] + accB[ntl][2], accA[ntl][3] + accB[ntl][3]);
        }
    }
}

// =============== Kernel 2: warp-MMA tf32 attention + fused GN ================
// CTA = 64 query rows, 4 warps x 16 rows, 128 threads, grid 256. Key tiles 64.
// k0-outer MMA loops (independent accumulators), S aliases Qs, GroupNorm fused
// into the epilogue via quad shuffles, transposed store directly to out.
#define LDP 68   // pad for Q/K/S
#define LDV 72   // pad for V

#define SM_BINV 0
#define SM_QS   64                      // [64][LDP]; reused as S buffer
#define SM_KS   (SM_QS + 64 * LDP)      // [64][LDP]
#define SM_VS   (SM_KS + 64 * LDP)      // [64][LDV]
#define ATTN_SMEM ((SM_VS + 64 * LDV) * 4)   // 53504 B

__global__ __launch_bounds__(128, 2) void attn_kernel(
    const float* __restrict__ gw, const float* __restrict__ gb,
    float* __restrict__ out)
{
    extern __shared__ float sm[];
    float* binv = sm + SM_BINV;
    float* Qs   = sm + SM_QS;
    float* Ks   = sm + SM_KS;
    float* Vs   = sm + SM_VS;

    const int tid  = threadIdx.x;
    const int lane = tid & 31;
    const int w    = tid >> 5;
    const int gi   = lane >> 2;   // 0..7
    const int ti4  = lane & 3;    // 0..3

    const int r0 = blockIdx.x * 64;
    const int b  = r0 >> 13;
    const int t0 = r0 & (T_SEQ - 1);
    const int bT = b << 13;

    if (tid < 64) binv[tid] = exp2f(-(float)tid * L2G);   // gamma^-j

    // ---- stage Q (tf32) ----
    for (int idx = tid; idx < 64 * 16; idx += 128) {
        int row = idx >> 4, c4 = (idx & 15) << 2;
        float4 v = *(const float4*)&g_Q[(r0 + row) * 64 + c4];
        v.x = to_tf32(v.x); v.y = to_tf32(v.y); v.z = to_tf32(v.z); v.w = to_tf32(v.w);
        *(float4*)&Qs[row * LDP + c4] = v;
    }
    __syncthreads();

    // ---- Q fragments, register-resident for all tiles ----
    const int qr = w * 16;
    unsigned qa[8][4];
    #pragma unroll
    for (int k0 = 0; k0 < 8; k0++) {
        int base = (qr + gi) * LDP + k0 * 8 + ti4;
        qa[k0][0] = __float_as_uint(Qs[base]);
        qa[k0][1] = __float_as_uint(Qs[base + 8 * LDP]);
        qa[k0][2] = __float_as_uint(Qs[base + 4]);
        qa[k0][3] = __float_as_uint(Qs[base + 8 * LDP + 4]);
    }

    float o[8][4];
    #pragma unroll
    for (int nt = 0; nt < 8; nt++)
        #pragma unroll
        for (int u = 0; u < 4; u++) o[nt][u] = 0.f;

    float* sw = Qs + qr * LDP;      // warp-private S buffer (aliases this warp's Q rows)
    int ks = t0 - WIN; if (ks < 0) ks = 0;

    for (int s0 = ks; s0 < t0 + 64; s0 += 64) {
        // ---- stage K, V tiles (tf32) ----
        for (int idx = tid; idx < 64 * 16; idx += 128) {
            int key = idx >> 4, c4 = (idx & 15) << 2;
            float4 kv = *(const float4*)&g_K[(bT + s0 + key) * 64 + c4];
            kv.x = to_tf32(kv.x); kv.y = to_tf32(kv.y);
            kv.z = to_tf32(kv.z); kv.w = to_tf32(kv.w);
            *(float4*)&Ks[key * LDP + c4] = kv;
            float4 vv = *(const float4*)&g_V[(bT + s0 + key) * 64 + c4];
            vv.x = to_tf32(vv.x); vv.y = to_tf32(vv.y);
            vv.z = to_tf32(vv.z); vv.w = to_tf32(vv.w);
            *(float4*)&Vs[key * LDV + c4] = vv;
        }
        __syncthreads();

        const int   dr0 = t0 + qr + gi - s0;          // iglob - s0, row a
        const float ai0 = exp2f((float)dr0 * L2G);
        const float ai1 = exp2f((float)(dr0 + 8) * L2G);

        // ---- stage 1: S = Q K^T (k0-outer: independent accumulators) ----
        float s[8][4];
        #pragma unroll
        for (int nt = 0; nt < 8; nt++)
            #pragma unroll
            for (int u = 0; u < 4; u++) s[nt][u] = 0.f;

        #pragma unroll
        for (int k0 = 0; k0 < 8; k0++) {
            #pragma unroll
            for (int nt = 0; nt < 8; nt++) {
                int ba = (nt * 8 + gi) * LDP + k0 * 8 + ti4;
                unsigned b0 = __float_as_uint(Ks[ba]);
                unsigned b1 = __float_as_uint(Ks[ba + 4]);
                mma_tf32(s[nt][0], s[nt][1], s[nt][2], s[nt][3],
                         qa[k0][0], qa[k0][1], qa[k0][2], qa[k0][3], b0, b1);
            }
        }

        // ---- decay + causal mask epilogue, store tf32 to S buffer ----
        #pragma unroll
        for (int nt = 0; nt < 8; nt++) {
            const int je = nt * 8 + 2 * ti4, jo = je + 1;
            const float be = binv[je], bo = binv[jo];
            float c0 = (dr0     >= je) ? s[nt][0] * ai0 * be : 0.f;
            float c1 = (dr0     >= jo) ? s[nt][1] * ai0 * bo : 0.f;
            float c2 = (dr0 + 8 >= je) ? s[nt][2] * ai1 * be : 0.f;
            float c3 = (dr0 + 8 >= jo) ? s[nt][3] * ai1 * bo : 0.f;
            *(float2*)&sw[gi * LDP + je]       = make_float2(to_tf32(c0), to_tf32(c1));
            *(float2*)&sw[(gi + 8) * LDP + je] = make_float2(to_tf32(c2), to_tf32(c3));
        }
        __syncwarp();

        // ---- A fragments of S ----
        unsigned sa[8][4];
        #pragma unroll
        for (int k0 = 0; k0 < 8; k0++) {
            int base = gi * LDP + k0 * 8 + ti4;
            sa[k0][0] = __float_as_uint(sw[base]);
            sa[k0][1] = __float_as_uint(sw[base + 8 * LDP]);
            sa[k0][2] = __float_as_uint(sw[base + 4]);
            sa[k0][3] = __float_as_uint(sw[base + 8 * LDP + 4]);
        }

        // ---- stage 2: O += S V (k0-outer: independent accumulators) ----
        #pragma unroll
        for (int k0 = 0; k0 < 8; k0++) {
            #pragma unroll
            for (int nt = 0; nt < 8; nt++) {
                int va = (k0 * 8 + ti4) * LDV + nt * 8 + gi;
                unsigned b0 = __float_as_uint(Vs[va]);
                unsigned b1 = __float_as_uint(Vs[va + 4 * LDV]);
                mma_tf32(o[nt][0], o[nt][1], o[nt][2], o[nt][3],
                         sa[k0][0], sa[k0][1], sa[k0][2], sa[k0][3], b0, b1);
            }
        }
        __syncthreads();
    }

    // ================= fused GroupNorm epilogue + transposed store ===========
    // Group nt = channels 8nt..8nt+7 = o[nt][0..1] (rows lo) / o[nt][2..3] (rows hi)
    // spread over the 4 quad lanes (ti4). Quad shuffles give sum / sum-of-squares.
    const int t_lo = t0 + qr + gi;
    float* outb = out + (size_t)b * T_SEQ * 64;

    #pragma unroll
    for (int nt = 0; nt < 8; nt++) {
        float sl = o[nt][0] + o[nt][1];
        float ql = fmaf(o[nt][0], o[nt][0], o[nt][1] * o[nt][1]);
        float sh = o[nt][2] + o[nt][3];
        float qh = fmaf(o[nt][2], o[nt][2], o[nt][3] * o[nt][3]);
        sl += __shfl_xor_sync(0xffffffffu, sl, 1);
        ql += __shfl_xor_sync(0xffffffffu, ql, 1);
        sh += __shfl_xor_sync(0xffffffffu, sh, 1);
        qh += __shfl_xor_sync(0xffffffffu, qh, 1);
        sl += __shfl_xor_sync(0xffffffffu, sl, 2);
        ql += __shfl_xor_sync(0xffffffffu, ql, 2);
        sh += __shfl_xor_sync(0xffffffffu, sh, 2);
        qh += __shfl_xor_sync(0xffffffffu, qh, 2);

        float mul = sl * 0.125f, muh = sh * 0.125f;
        float rl = rsqrtf(fmaf(-mul, mul, ql * 0.125f) + 1e-6f);
        float rh = rsqrtf(fmaf(-muh, muh, qh * 0.125f) + 1e-6f);

        const int c0 = nt * 8 + 2 * ti4, c1 = c0 + 1;
        const float w0 = gw[c0], w1 = gw[c1];
        const float b0 = gb[c0], b1 = gb[c1];
        outb[(size_t)c0 * T_SEQ + t_lo]     = (o[nt][0] - mul) * rl * w0 + b0;
        outb[(size_t)c1 * T_SEQ + t_lo]     = (o[nt][1] - mul) * rl * w1 + b1;
        outb[(size_t)c0 * T_SEQ + t_lo + 8] = (o[nt][2] - muh) * rh * w0 + b0;
        outb[(size_t)c1 * T_SEQ + t_lo + 8] = (o[nt][3] - muh) * rh * w1 + b1;
    }
}

// =============================================================================
extern "C" void kernel_launch(void* const* d_in, const int* in_sizes, int n_in,
                              void* d_out, int out_size)
{
    (void)in_sizes; (void)n_in; (void)out_size;
    const float* X  = (const float*)d_in[0];
    const float* WQ = (const float*)d_in[1];
    const float* WK = (const float*)d_in[2];
    const float* WV = (const float*)d_in[3];
    const float* gw = (const float*)d_in[4];
    const float* gb = (const float*)d_in[5];
    float* out = (float*)d_out;

    cudaFuncSetAttribute(proj_kernel, cudaFuncAttributeMaxDynamicSharedMemorySize, PROJ_SMEM);
    cudaFuncSetAttribute(attn_kernel, cudaFuncAttributeMaxDynamicSharedMemorySize, ATTN_SMEM);

    proj_kernel<<<NROWS / 64, 256, PROJ_SMEM>>>(X, WQ, WK, WV);
    attn_kernel<<<NROWS / 64, 128, ATTN_SMEM>>>(gw, gb, out);
}